// round 10
// baseline (speedup 1.0000x reference)
#include <cuda_runtime.h>
#include <cstdint>
#include <cstddef>

#define BATCH 16
#define CIN   256
#define COUT  256
#define NPIX  4096
#define KTOT  2304
#define NHID  65
#define NCHUNK 72   // 2304 / 32

// ---------------- device scratch (sanctioned: __device__ globals) ----------
__device__ float g_pooled[BATCH * CIN];
__device__ float g_att[BATCH * 4];
__device__ float g_aggw[(size_t)BATCH * COUT * KTOT];   // [b][co][k], tf32-rounded
__device__ float g_xr[(size_t)BATCH * CIN * NPIX];      // tf32-rounded copy of x

// ---------------- helpers ----------------------------------------------------
static __device__ __forceinline__ uint32_t smem_u32(const void* p) {
    uint32_t a;
    asm("{ .reg .u64 t; cvta.to.shared.u64 t, %1; cvt.u32.u64 %0, t; }" : "=r"(a) : "l"(p));
    return a;
}
static __device__ __forceinline__ float round_tf32(float v) {
    uint32_t o;
    asm("cvt.rna.tf32.f32 %0, %1;" : "=r"(o) : "f"(v));
    return __uint_as_float(o);
}
// SW128-style XOR swizzle at 16B granularity within 1024B (8-row) blocks
static __device__ __forceinline__ uint32_t sw128(uint32_t off) {
    return off ^ ((off >> 3) & 0x70);
}
static __device__ __forceinline__ void ldsm_x4(uint32_t r[4], uint32_t addr) {
    asm volatile("ldmatrix.sync.aligned.m8n8.x4.shared.b16 {%0,%1,%2,%3}, [%4];"
                 : "=r"(r[0]), "=r"(r[1]), "=r"(r[2]), "=r"(r[3]) : "r"(addr));
}
static __device__ __forceinline__ void mma_tf32(float d[4], const uint32_t a[4],
                                                uint32_t b0, uint32_t b1) {
    asm volatile(
        "mma.sync.aligned.m16n8k8.row.col.f32.tf32.tf32.f32 "
        "{%0,%1,%2,%3}, {%4,%5,%6,%7}, {%8,%9}, {%0,%1,%2,%3};"
        : "+f"(d[0]), "+f"(d[1]), "+f"(d[2]), "+f"(d[3])
        : "r"(a[0]), "r"(a[1]), "r"(a[2]), "r"(a[3]), "r"(b0), "r"(b1));
}

// ---------------- kernel 1: global average pool -----------------------------
__global__ void pool_kernel(const float* __restrict__ x) {
    int c = blockIdx.x, b = blockIdx.y, t = threadIdx.x;
    const float4* p = reinterpret_cast<const float4*>(x + ((size_t)(b * CIN + c)) * NPIX);
    float s = 0.f;
#pragma unroll
    for (int i = 0; i < 8; i++) {
        float4 v = p[t + 128 * i];
        s += v.x + v.y + v.z + v.w;
    }
#pragma unroll
    for (int d = 16; d; d >>= 1) s += __shfl_xor_sync(0xffffffffu, s, d);
    __shared__ float ws[4];
    if ((t & 31) == 0) ws[t >> 5] = s;
    __syncthreads();
    if (t == 0) g_pooled[b * CIN + c] = (ws[0] + ws[1] + ws[2] + ws[3]) * (1.0f / NPIX);
}

// ---------------- kernel 2: attention MLP + softmax(logits/34) --------------
__global__ void att_kernel(const float* __restrict__ w1, const float* __restrict__ w2,
                           const float* __restrict__ b2) {
    int b = blockIdx.x, t = threadIdx.x;
    __shared__ float pl[CIN], h[NHID], lg[4];
    for (int i = t; i < CIN; i += blockDim.x) pl[i] = g_pooled[b * CIN + i];
    __syncthreads();
    if (t < NHID) {
        float s = 0.f;
        for (int c = 0; c < CIN; c++) s += pl[c] * w1[t * CIN + c];
        h[t] = fmaxf(s, 0.f);
    }
    __syncthreads();
    if (t < 4) {
        float s = b2[t];
        for (int j = 0; j < NHID; j++) s += h[j] * w2[t * NHID + j];
        lg[t] = s * (1.0f / 34.0f);
    }
    __syncthreads();
    if (t == 0) {
        float m = fmaxf(fmaxf(lg[0], lg[1]), fmaxf(lg[2], lg[3]));
        float e[4], sum = 0.f;
        for (int k = 0; k < 4; k++) { e[k] = expf(lg[k] - m); sum += e[k]; }
        float inv = 1.0f / sum;
        for (int k = 0; k < 4; k++) g_att[b * 4 + k] = e[k] * inv;
    }
}

// ---------------- kernel 3: aggregate bank -> g_aggw[b][co][rs*256+ci] ------
// weight layout: (K=4, co, ci, 3, 3) -> offset ((k*256+co)*2304) + ci*9 + rs
__global__ void agg_kernel(const float* __restrict__ weight) {
    int co = blockIdx.x, t = threadIdx.x;
    __shared__ float w[4][KTOT];
    for (int k = 0; k < 4; k++)
        for (int i = t; i < KTOT; i += 256)
            w[k][i] = weight[((size_t)(k * COUT + co)) * KTOT + i];
    __syncthreads();
    for (int b = 0; b < BATCH; b++) {
        float a0 = g_att[b * 4 + 0], a1 = g_att[b * 4 + 1];
        float a2 = g_att[b * 4 + 2], a3 = g_att[b * 4 + 3];
        float* dst = g_aggw + ((size_t)(b * COUT + co)) * KTOT;
        for (int i = t; i < KTOT; i += 256) {
            int ci = i & 255, rs = i >> 8;
            int si = ci * 9 + rs;  // stride-9 smem read: conflict-free (gcd(9,32)=1)
            dst[i] = round_tf32(a0 * w[0][si] + a1 * w[1][si] + a2 * w[2][si] + a3 * w[3][si]);
        }
    }
}

// ---------------- kernel 4: tf32-round x ------------------------------------
__global__ void roundx_kernel(const float* __restrict__ x) {
    size_t i = (size_t)blockIdx.x * 256 + threadIdx.x;
    float4 v = reinterpret_cast<const float4*>(x)[i];
    v.x = round_tf32(v.x); v.y = round_tf32(v.y);
    v.z = round_tf32(v.z); v.w = round_tf32(v.w);
    reinterpret_cast<float4*>(g_xr)[i] = v;
}

// ---------------- kernel 5: implicit-GEMM conv (mma.sync tf32) --------------
// CTA tile: M=128 co, N=128 pixels (2 image rows). 8 warps = 2(M) x 4(N),
// warp tile 64x32. K chunked 72 x 32; chunk kc has fixed (r,s) = kc/8 (/3, %3)
// and ci0 = (kc%8)*32, so im2col is a shifted predicated coalesced read.
// Smem per buffer: A [co][k] 128x128B, B [pix][k] 128x128B, XOR-swizzled.
__global__ void __launch_bounds__(256, 1) conv_kernel(float* __restrict__ out) {
    extern __shared__ char dsm_raw[];
    char* dyn = (char*)(((uintptr_t)dsm_raw + 1023) & ~(uintptr_t)1023);
    // buffers: buf s: A at s*32768, B at s*32768 + 16384

    int t = threadIdx.x, wid = t >> 5, lane = t & 31;
    int wm = wid >> 2, wn = wid & 3;
    int b = blockIdx.z, co0 = blockIdx.y * 128, pix0 = blockIdx.x * 128;
    int y0 = pix0 >> 6;

    const float* A = g_aggw + ((size_t)(b * COUT + co0)) * KTOT;
    const float* X = g_xr + (size_t)b * CIN * NPIX;

    // B-load thread mapping: kl = k row (0..31), px = pixel sub-index (0..7)
    int kl = 4 * wid + (lane >> 3);
    int px = lane & 7;

    // ldmatrix per-lane row/byte offsets (relative to tile base)
    uint32_t rowA[4], rowB[2];
#pragma unroll
    for (int i = 0; i < 4; i++)
        rowA[i] = (uint32_t)((wm * 64 + i * 16 + (lane & 7) + ((lane >> 3) & 1) * 8) * 128
                             + ((lane >> 4) & 1) * 16);
#pragma unroll
    for (int q = 0; q < 2; q++)
        rowB[q] = (uint32_t)((wn * 32 + (q * 2 + ((lane >> 4) & 1)) * 8 + (lane & 7)) * 128
                             + ((lane >> 3) & 1) * 16);

    float d[4][4][4];
#pragma unroll
    for (int i = 0; i < 4; i++)
#pragma unroll
        for (int j = 0; j < 4; j++)
#pragma unroll
            for (int r = 0; r < 4; r++) d[i][j][r] = 0.f;

    // ---- load chunk 0 straight into buffer 0 ----
    {
        const float* Ac = A;
#pragma unroll
        for (int j = 0; j < 4; j++) {
            int f = t + 256 * j;
            int co = f >> 3, kq = f & 7;
            float4 v = *reinterpret_cast<const float4*>(Ac + (size_t)co * KTOT + kq * 4);
            *reinterpret_cast<float4*>(dyn + sw128((uint32_t)(co * 128 + kq * 16))) = v;
        }
        const float* Xc = X + (size_t)kl * NPIX;   // rs=0 -> dy=-1, dx=-1; ci0=0
#pragma unroll
        for (int j = 0; j < 16; j++) {
            int p = j * 8 + px;
            int yy = y0 - 1 + (p >> 6);
            int xx = (p & 63) - 1;
            float v = 0.f;
            if ((unsigned)yy < 64u && (unsigned)xx < 64u) v = Xc[yy * 64 + xx];
            *reinterpret_cast<float*>(dyn + 16384 + sw128((uint32_t)(p * 128 + kl * 4))) = v;
        }
    }
    __syncthreads();

    for (int kc = 0; kc < NCHUNK; kc++) {
        char* cur = dyn + (kc & 1) * 32768;
        char* nxt = dyn + ((kc + 1) & 1) * 32768;

        // ---- prefetch chunk kc+1 into registers (LDG overlaps compute) ----
        float4 pa[4];
        float pb[16];
        bool have_next = (kc + 1 < NCHUNK);
        if (have_next) {
            int kn = kc + 1;
            const float* Ac = A + kn * 32;
#pragma unroll
            for (int j = 0; j < 4; j++) {
                int f = t + 256 * j;
                int co = f >> 3, kq = f & 7;
                pa[j] = *reinterpret_cast<const float4*>(Ac + (size_t)co * KTOT + kq * 4);
            }
            int rs = kn >> 3;
            int dy = rs / 3 - 1, dx = rs % 3 - 1;
            const float* Xc = X + (size_t)(((kn & 7) << 5) + kl) * NPIX;
            int yb = y0 + dy;
#pragma unroll
            for (int j = 0; j < 16; j++) {
                int p = j * 8 + px;
                int yy = yb + (p >> 6);
                int xx = (p & 63) + dx;
                float v = 0.f;
                if ((unsigned)yy < 64u && (unsigned)xx < 64u) v = Xc[yy * 64 + xx];
                pb[j] = v;
            }
        }

        // ---- compute on current buffer ----
        uint32_t a_base = smem_u32(cur);
        uint32_t b_base = a_base + 16384;
#pragma unroll
        for (int s = 0; s < 4; s++) {
            uint32_t af[4][4];
#pragma unroll
            for (int i = 0; i < 4; i++) ldsm_x4(af[i], a_base + sw128(rowA[i] + s * 32));
            uint32_t bf[2][4];
#pragma unroll
            for (int q = 0; q < 2; q++) ldsm_x4(bf[q], b_base + sw128(rowB[q] + s * 32));
#pragma unroll
            for (int i = 0; i < 4; i++)
#pragma unroll
                for (int j = 0; j < 4; j++)
                    mma_tf32(d[i][j], af[i], bf[j >> 1][(j & 1) * 2], bf[j >> 1][(j & 1) * 2 + 1]);
        }

        // ---- commit prefetched chunk to the other buffer ----
        if (have_next) {
#pragma unroll
            for (int j = 0; j < 4; j++) {
                int f = t + 256 * j;
                int co = f >> 3, kq = f & 7;
                *reinterpret_cast<float4*>(nxt + sw128((uint32_t)(co * 128 + kq * 16))) = pa[j];
            }
#pragma unroll
            for (int j = 0; j < 16; j++) {
                int p = j * 8 + px;
                *reinterpret_cast<float*>(nxt + 16384 + sw128((uint32_t)(p * 128 + kl * 4))) = pb[j];
            }
        }
        __syncthreads();
    }

    // ---- epilogue: write accumulators ----
    int g = lane >> 2, tig = lane & 3;
    float* ob = out + ((size_t)(b * COUT + co0 + wm * 64 + g)) * NPIX
              + pix0 + wn * 32 + tig * 2;
#pragma unroll
    for (int i = 0; i < 4; i++) {
#pragma unroll
        for (int j = 0; j < 4; j++) {
            *reinterpret_cast<float2*>(ob + (size_t)(i * 16) * NPIX + j * 8) =
                make_float2(d[i][j][0], d[i][j][1]);
            *reinterpret_cast<float2*>(ob + (size_t)(i * 16 + 8) * NPIX + j * 8) =
                make_float2(d[i][j][2], d[i][j][3]);
        }
    }
}

// ---------------- host launcher ---------------------------------------------
extern "C" void kernel_launch(void* const* d_in, const int* in_sizes, int n_in,
                              void* d_out, int out_size) {
    const float* x  = (const float*)d_in[0];
    const float* w  = (const float*)d_in[1];
    const float* w1 = (const float*)d_in[2];
    const float* w2 = (const float*)d_in[3];
    const float* b2 = (const float*)d_in[4];
    float* out = (float*)d_out;

    const int dyn_smem = 2 * 32768 + 1024;
    static int cfg_done = 0;
    if (!cfg_done) {
        cudaFuncSetAttribute(conv_kernel, cudaFuncAttributeMaxDynamicSharedMemorySize, dyn_smem);
        cfg_done = 1;
    }

    pool_kernel<<<dim3(CIN, BATCH), 128>>>(x);
    att_kernel<<<BATCH, 128>>>(w1, w2, b2);
    agg_kernel<<<COUT, 256>>>(w);
    roundx_kernel<<<(BATCH * CIN * NPIX) / (256 * 4), 256>>>(x);
    conv_kernel<<<dim3(NPIX / 128, COUT / 128, BATCH), 256, dyn_smem>>>(out);
}

// round 13
// speedup vs baseline: 1.0012x; 1.0012x over previous
#include <cuda_runtime.h>
#include <cstdint>
#include <cstddef>

#define BATCH 16
#define CIN   256
#define COUT  256
#define NPIX  4096
#define KTOT  2304
#define NHID  65
#define NCHUNK 72   // 2304 / 32

// ---------------- device scratch (sanctioned: __device__ globals) ----------
__device__ float g_pooled[BATCH * CIN];
__device__ float g_att[BATCH * 4];
__device__ float g_aggw[(size_t)BATCH * COUT * KTOT];   // [b][co][k], tf32-rounded
__device__ float g_xr[(size_t)BATCH * CIN * NPIX];      // tf32-rounded copy of x

// ---------------- helpers ----------------------------------------------------
static __device__ __forceinline__ uint32_t smem_u32(const void* p) {
    uint32_t a;
    asm("{ .reg .u64 t; cvta.to.shared.u64 t, %1; cvt.u32.u64 %0, t; }" : "=r"(a) : "l"(p));
    return a;
}
static __device__ __forceinline__ float round_tf32(float v) {
    uint32_t o;
    asm("cvt.rna.tf32.f32 %0, %1;" : "=r"(o) : "f"(v));
    return __uint_as_float(o);
}
// SW128-style XOR swizzle at 16B granularity within 1024B (8-row) blocks
static __device__ __forceinline__ uint32_t sw128(uint32_t off) {
    return off ^ ((off >> 3) & 0x70);
}
static __device__ __forceinline__ void ldsm_x4(uint32_t r[4], uint32_t addr) {
    asm volatile("ldmatrix.sync.aligned.m8n8.x4.shared.b16 {%0,%1,%2,%3}, [%4];"
                 : "=r"(r[0]), "=r"(r[1]), "=r"(r[2]), "=r"(r[3]) : "r"(addr));
}
static __device__ __forceinline__ void mma_tf32(float d[4], const uint32_t a[4],
                                                uint32_t b0, uint32_t b1) {
    asm volatile(
        "mma.sync.aligned.m16n8k8.row.col.f32.tf32.tf32.f32 "
        "{%0,%1,%2,%3}, {%4,%5,%6,%7}, {%8,%9}, {%0,%1,%2,%3};"
        : "+f"(d[0]), "+f"(d[1]), "+f"(d[2]), "+f"(d[3])
        : "r"(a[0]), "r"(a[1]), "r"(a[2]), "r"(a[3]), "r"(b0), "r"(b1));
}

// ---------------- kernel 1: global average pool -----------------------------
__global__ void pool_kernel(const float* __restrict__ x) {
    int c = blockIdx.x, b = blockIdx.y, t = threadIdx.x;
    const float4* p = reinterpret_cast<const float4*>(x + ((size_t)(b * CIN + c)) * NPIX);
    float s = 0.f;
#pragma unroll
    for (int i = 0; i < 8; i++) {
        float4 v = p[t + 128 * i];
        s += v.x + v.y + v.z + v.w;
    }
#pragma unroll
    for (int d = 16; d; d >>= 1) s += __shfl_xor_sync(0xffffffffu, s, d);
    __shared__ float ws[4];
    if ((t & 31) == 0) ws[t >> 5] = s;
    __syncthreads();
    if (t == 0) g_pooled[b * CIN + c] = (ws[0] + ws[1] + ws[2] + ws[3]) * (1.0f / NPIX);
}

// ---------------- kernel 2: attention MLP + softmax(logits/34) --------------
__global__ void att_kernel(const float* __restrict__ w1, const float* __restrict__ w2,
                           const float* __restrict__ b2) {
    int b = blockIdx.x, t = threadIdx.x;
    __shared__ float pl[CIN], h[NHID], lg[4];
    for (int i = t; i < CIN; i += blockDim.x) pl[i] = g_pooled[b * CIN + i];
    __syncthreads();
    if (t < NHID) {
        float s = 0.f;
        for (int c = 0; c < CIN; c++) s += pl[c] * w1[t * CIN + c];
        h[t] = fmaxf(s, 0.f);
    }
    __syncthreads();
    if (t < 4) {
        float s = b2[t];
        for (int j = 0; j < NHID; j++) s += h[j] * w2[t * NHID + j];
        lg[t] = s * (1.0f / 34.0f);
    }
    __syncthreads();
    if (t == 0) {
        float m = fmaxf(fmaxf(lg[0], lg[1]), fmaxf(lg[2], lg[3]));
        float e[4], sum = 0.f;
        for (int k = 0; k < 4; k++) { e[k] = expf(lg[k] - m); sum += e[k]; }
        float inv = 1.0f / sum;
        for (int k = 0; k < 4; k++) g_att[b * 4 + k] = e[k] * inv;
    }
}

// ---------------- kernel 3: aggregate bank -> g_aggw[b][co][rs*256+ci] ------
// weight layout: (K=4, co, ci, 3, 3) -> offset ((k*256+co)*2304) + ci*9 + rs
__global__ void agg_kernel(const float* __restrict__ weight) {
    int co = blockIdx.x, t = threadIdx.x;
    __shared__ float w[4][KTOT];
    for (int k = 0; k < 4; k++)
        for (int i = t; i < KTOT; i += 256)
            w[k][i] = weight[((size_t)(k * COUT + co)) * KTOT + i];
    __syncthreads();
    for (int b = 0; b < BATCH; b++) {
        float a0 = g_att[b * 4 + 0], a1 = g_att[b * 4 + 1];
        float a2 = g_att[b * 4 + 2], a3 = g_att[b * 4 + 3];
        float* dst = g_aggw + ((size_t)(b * COUT + co)) * KTOT;
        for (int i = t; i < KTOT; i += 256) {
            int ci = i & 255, rs = i >> 8;
            int si = ci * 9 + rs;  // stride-9 smem read: conflict-free (gcd(9,32)=1)
            dst[i] = round_tf32(a0 * w[0][si] + a1 * w[1][si] + a2 * w[2][si] + a3 * w[3][si]);
        }
    }
}

// ---------------- kernel 4: tf32-round x ------------------------------------
__global__ void roundx_kernel(const float* __restrict__ x) {
    size_t i = (size_t)blockIdx.x * 256 + threadIdx.x;
    float4 v = reinterpret_cast<const float4*>(x)[i];
    v.x = round_tf32(v.x); v.y = round_tf32(v.y);
    v.z = round_tf32(v.z); v.w = round_tf32(v.w);
    reinterpret_cast<float4*>(g_xr)[i] = v;
}

// ---------------- kernel 5: implicit-GEMM conv (mma.sync tf32) --------------
// CTA tile: M=128 co, N=128 pixels (2 image rows). 8 warps = 2(M) x 4(N),
// warp tile 64x32. K chunked 72 x 32; chunk kc has fixed (r,s) = kc/8 (/3, %3)
// and ci0 = (kc%8)*32, so im2col is a shifted predicated coalesced read.
// Smem per buffer: A [co][k] 128x128B, B [pix][k] 128x128B, XOR-swizzled.
__global__ void __launch_bounds__(256, 1) conv_kernel(float* __restrict__ out) {
    extern __shared__ char dsm_raw[];
    char* dyn = (char*)(((uintptr_t)dsm_raw + 1023) & ~(uintptr_t)1023);
    // buffers: buf s: A at s*32768, B at s*32768 + 16384

    int t = threadIdx.x, wid = t >> 5, lane = t & 31;
    int wm = wid >> 2, wn = wid & 3;
    int b = blockIdx.z, co0 = blockIdx.y * 128, pix0 = blockIdx.x * 128;
    int y0 = pix0 >> 6;

    const float* A = g_aggw + ((size_t)(b * COUT + co0)) * KTOT;
    const float* X = g_xr + (size_t)b * CIN * NPIX;

    // B-load thread mapping: kl = k row (0..31), px = pixel sub-index (0..7)
    int kl = 4 * wid + (lane >> 3);
    int px = lane & 7;

    // ldmatrix per-lane row/byte offsets (relative to tile base)
    uint32_t rowA[4], rowB[2];
#pragma unroll
    for (int i = 0; i < 4; i++)
        rowA[i] = (uint32_t)((wm * 64 + i * 16 + (lane & 7) + ((lane >> 3) & 1) * 8) * 128
                             + ((lane >> 4) & 1) * 16);
#pragma unroll
    for (int q = 0; q < 2; q++)
        rowB[q] = (uint32_t)((wn * 32 + (q * 2 + ((lane >> 4) & 1)) * 8 + (lane & 7)) * 128
                             + ((lane >> 3) & 1) * 16);

    float d[4][4][4];
#pragma unroll
    for (int i = 0; i < 4; i++)
#pragma unroll
        for (int j = 0; j < 4; j++)
#pragma unroll
            for (int r = 0; r < 4; r++) d[i][j][r] = 0.f;

    // ---- load chunk 0 straight into buffer 0 ----
    {
        const float* Ac = A;
#pragma unroll
        for (int j = 0; j < 4; j++) {
            int f = t + 256 * j;
            int co = f >> 3, kq = f & 7;
            float4 v = *reinterpret_cast<const float4*>(Ac + (size_t)co * KTOT + kq * 4);
            *reinterpret_cast<float4*>(dyn + sw128((uint32_t)(co * 128 + kq * 16))) = v;
        }
        const float* Xc = X + (size_t)kl * NPIX;   // rs=0 -> dy=-1, dx=-1; ci0=0
#pragma unroll
        for (int j = 0; j < 16; j++) {
            int p = j * 8 + px;
            int yy = y0 - 1 + (p >> 6);
            int xx = (p & 63) - 1;
            float v = 0.f;
            if ((unsigned)yy < 64u && (unsigned)xx < 64u) v = Xc[yy * 64 + xx];
            *reinterpret_cast<float*>(dyn + 16384 + sw128((uint32_t)(p * 128 + kl * 4))) = v;
        }
    }
    __syncthreads();

    for (int kc = 0; kc < NCHUNK; kc++) {
        char* cur = dyn + (kc & 1) * 32768;
        char* nxt = dyn + ((kc + 1) & 1) * 32768;

        // ---- prefetch chunk kc+1 into registers (LDG overlaps compute) ----
        float4 pa[4];
        float pb[16];
        bool have_next = (kc + 1 < NCHUNK);
        if (have_next) {
            int kn = kc + 1;
            const float* Ac = A + kn * 32;
#pragma unroll
            for (int j = 0; j < 4; j++) {
                int f = t + 256 * j;
                int co = f >> 3, kq = f & 7;
                pa[j] = *reinterpret_cast<const float4*>(Ac + (size_t)co * KTOT + kq * 4);
            }
            int rs = kn >> 3;
            int dy = rs / 3 - 1, dx = rs % 3 - 1;
            const float* Xc = X + (size_t)(((kn & 7) << 5) + kl) * NPIX;
            int yb = y0 + dy;
#pragma unroll
            for (int j = 0; j < 16; j++) {
                int p = j * 8 + px;
                int yy = yb + (p >> 6);
                int xx = (p & 63) + dx;
                float v = 0.f;
                if ((unsigned)yy < 64u && (unsigned)xx < 64u) v = Xc[yy * 64 + xx];
                pb[j] = v;
            }
        }

        // ---- compute on current buffer ----
        uint32_t a_base = smem_u32(cur);
        uint32_t b_base = a_base + 16384;
#pragma unroll
        for (int s = 0; s < 4; s++) {
            uint32_t af[4][4];
#pragma unroll
            for (int i = 0; i < 4; i++) ldsm_x4(af[i], a_base + sw128(rowA[i] + s * 32));
            uint32_t bf[2][4];
#pragma unroll
            for (int q = 0; q < 2; q++) ldsm_x4(bf[q], b_base + sw128(rowB[q] + s * 32));
#pragma unroll
            for (int i = 0; i < 4; i++)
#pragma unroll
                for (int j = 0; j < 4; j++)
                    mma_tf32(d[i][j], af[i], bf[j >> 1][(j & 1) * 2], bf[j >> 1][(j & 1) * 2 + 1]);
        }

        // ---- commit prefetched chunk to the other buffer ----
        if (have_next) {
#pragma unroll
            for (int j = 0; j < 4; j++) {
                int f = t + 256 * j;
                int co = f >> 3, kq = f & 7;
                *reinterpret_cast<float4*>(nxt + sw128((uint32_t)(co * 128 + kq * 16))) = pa[j];
            }
#pragma unroll
            for (int j = 0; j < 16; j++) {
                int p = j * 8 + px;
                *reinterpret_cast<float*>(nxt + 16384 + sw128((uint32_t)(p * 128 + kl * 4))) = pb[j];
            }
        }
        __syncthreads();
    }

    // ---- epilogue: write accumulators ----
    int g = lane >> 2, tig = lane & 3;
    float* ob = out + ((size_t)(b * COUT + co0 + wm * 64 + g)) * NPIX
              + pix0 + wn * 32 + tig * 2;
#pragma unroll
    for (int i = 0; i < 4; i++) {
#pragma unroll
        for (int j = 0; j < 4; j++) {
            *reinterpret_cast<float2*>(ob + (size_t)(i * 16) * NPIX + j * 8) =
                make_float2(d[i][j][0], d[i][j][1]);
            *reinterpret_cast<float2*>(ob + (size_t)(i * 16 + 8) * NPIX + j * 8) =
                make_float2(d[i][j][2], d[i][j][3]);
        }
    }
}

// ---------------- host launcher ---------------------------------------------
extern "C" void kernel_launch(void* const* d_in, const int* in_sizes, int n_in,
                              void* d_out, int out_size) {
    const float* x  = (const float*)d_in[0];
    const float* w  = (const float*)d_in[1];
    const float* w1 = (const float*)d_in[2];
    const float* w2 = (const float*)d_in[3];
    const float* b2 = (const float*)d_in[4];
    float* out = (float*)d_out;

    const int dyn_smem = 2 * 32768 + 1024;
    static int cfg_done = 0;
    if (!cfg_done) {
        cudaFuncSetAttribute(conv_kernel, cudaFuncAttributeMaxDynamicSharedMemorySize, dyn_smem);
        cfg_done = 1;
    }

    pool_kernel<<<dim3(CIN, BATCH), 128>>>(x);
    att_kernel<<<BATCH, 128>>>(w1, w2, b2);
    agg_kernel<<<COUT, 256>>>(w);
    roundx_kernel<<<(BATCH * CIN * NPIX) / (256 * 4), 256>>>(x);
    conv_kernel<<<dim3(NPIX / 128, COUT / 128, BATCH), 256, dyn_smem>>>(out);
}